// round 15
// baseline (speedup 1.0000x reference)
#include <cuda_runtime.h>
#include <cuda_fp16.h>
#include <cstdint>

#define BATCH 4096
#define INDIM 2048
#define HID   2048
#define KTOT  4096

#define BM 128
#define BN 128
#define BK 32
#define NSTG (KTOT / BK)                 // 128 k-chunks

#define ROWB 80                          // 64B data + 16B pad per row
#define TILE_BYTES (128 * ROWB)          // 10240
#define OFF_A 0
#define OFF_B TILE_BYTES
#define STAGE_BYTES (2 * TILE_BYTES)     // 20480
#define NPIPE 4
#define SMEM_BYTES (NPIPE * STAGE_BYTES) // 81920

#define DELTA    3e-3f
#define LIST_CAP (1u << 21)

// ---------------- device scratch ----------------
__device__ __half g_Ah[(size_t)BATCH * KTOT];    // [m][k]: fp16(X) | fp16(S)
__device__ __half g_Bh[(size_t)HID * KTOT];      // [n][k]: fp16(W^T) concat
__device__ __half g_Br[(size_t)HID * KTOT];      // [n][k]: fp16 residual (w - fp16(w))
__device__ uint32_t g_count;
__device__ uint32_t g_list[LIST_CAP];

// ---------------- helpers ----------------
__device__ __forceinline__ uint32_t s2u(const void* p) {
    uint32_t a;
    asm("{ .reg .u64 t; cvta.to.shared.u64 t, %1; cvt.u32.u64 %0, t; }"
        : "=r"(a) : "l"(p));
    return a;
}
__device__ __forceinline__ void cp16(uint32_t d, const void* s) {
    asm volatile("cp.async.cg.shared.global [%0], [%1], 16;" :: "r"(d), "l"(s));
}
__device__ __forceinline__ void ldm4(uint32_t* r, uint32_t addr) {
    asm volatile("ldmatrix.sync.aligned.m8n8.x4.shared.b16 {%0,%1,%2,%3}, [%4];"
                 : "=r"(r[0]), "=r"(r[1]), "=r"(r[2]), "=r"(r[3]) : "r"(addr));
}
__device__ __forceinline__ void mma16(float* d, const uint32_t* a, const uint32_t* b) {
    asm volatile(
        "mma.sync.aligned.m16n8k16.row.col.f32.f16.f16.f32 "
        "{%0,%1,%2,%3},{%4,%5,%6,%7},{%8,%9},{%0,%1,%2,%3};"
        : "+f"(d[0]), "+f"(d[1]), "+f"(d[2]), "+f"(d[3])
        : "r"(a[0]), "r"(a[1]), "r"(a[2]), "r"(a[3]), "r"(b[0]), "r"(b[1]));
}

// ---------------- pre-kernels ----------------
__global__ void build_a_k(const float* __restrict__ X, const float* __restrict__ S) {
    size_t i = (size_t)blockIdx.x * blockDim.x + threadIdx.x;   // half2 index
    if (i == 0) g_count = 0;
    const size_t n2 = (size_t)BATCH * KTOT / 2;
    if (i >= n2) return;
    const int m = (int)(i >> 11);
    const int k = (int)(i & 2047) * 2;
    float2 v;
    if (k < INDIM) v = *(const float2*)(X + (size_t)m * INDIM + k);
    else           v = *(const float2*)(S + (size_t)m * HID + (k - INDIM));
    ((__half2*)g_Ah)[i] = __floats2half2_rn(v.x, v.y);
}
__global__ void trans_w_k(const float* __restrict__ Wpsp,
                          const float* __restrict__ Wrec) {
    __shared__ float tile[32][33];
    const float* W = blockIdx.z ? Wrec : Wpsp;
    const int off = blockIdx.z ? INDIM : 0;
    const int n0 = blockIdx.x * 32, k0 = blockIdx.y * 32;
    const int tx = threadIdx.x, ty = threadIdx.y;
    #pragma unroll
    for (int r = ty; r < 32; r += 8)
        tile[r][tx] = W[(size_t)(k0 + r) * HID + n0 + tx];
    __syncthreads();
    #pragma unroll
    for (int r = ty; r < 32; r += 8) {
        float v = tile[tx][r];                    // = W[k0+tx][n0+r]
        size_t o = (size_t)(n0 + r) * KTOT + off + k0 + tx;
        __half h = __float2half_rn(v);
        g_Bh[o] = h;
        g_Br[o] = __float2half_rn(v - __half2float(h));   // Sterbenz-exact residual
    }
}

// ---------------- main fused GEMM + LIF + band detect (R8 config, unchanged) ----------------
__global__ void __launch_bounds__(256, 2)
gemm_lif(const float* __restrict__ S, const float* __restrict__ preC,
         const float* __restrict__ preV, const float* __restrict__ preTh,
         const float* __restrict__ mask, const float* __restrict__ bpsp,
         const float* __restrict__ brec, float* __restrict__ out, int sections)
{
    extern __shared__ char smem[];
    const uint32_t sb = s2u(smem);
    const int tid = threadIdx.x;
    const int lane = tid & 31, warp = tid >> 5;
    const int g = lane >> 2, t4 = lane & 3;
    const int wm = warp >> 2, wn = warp & 3;            // 2 x 4 warps, 64x32 tiles
    const int m0 = blockIdx.y * BM, n0 = blockIdx.x * BN;

    const uint32_t aoff = (uint32_t)((lane & 15) * ROWB + (lane >> 4) * 16);
    const uint32_t boff =
        (uint32_t)((((lane & 7) + ((lane >> 4) & 1) * 8)) * ROWB + ((lane >> 3) & 1) * 16);

    float acc[4][4][4];
    #pragma unroll
    for (int i = 0; i < 4; i++)
        #pragma unroll
        for (int j = 0; j < 4; j++)
            #pragma unroll
            for (int q = 0; q < 4; q++) acc[i][j][q] = 0.0f;

    auto load_stage = [&](int t) {
        const uint32_t base = sb + (uint32_t)((t & (NPIPE - 1)) * STAGE_BYTES);
        const int k0 = t * BK;
        #pragma unroll
        for (int i = 0; i < 2; i++) {
            const int u = tid + i * 256;
            const int r = u >> 2, c = u & 3;
            const uint32_t d = (uint32_t)(r * ROWB + c * 16);
            cp16(base + OFF_A + d, g_Ah + (size_t)(m0 + r) * KTOT + k0 + c * 8);
            cp16(base + OFF_B + d, g_Bh + (size_t)(n0 + r) * KTOT + k0 + c * 8);
        }
    };

    uint32_t fa[4][4], fb[4][2];
    auto compute_half = [&](uint32_t stb, int h) {
        const uint32_t kb = (uint32_t)(h * 32);
        #pragma unroll
        for (int mf = 0; mf < 4; mf++)
            ldm4(fa[mf], stb + OFF_A + (uint32_t)((wm * 64 + mf * 16) * ROWB) + kb + aoff);
        #pragma unroll
        for (int p = 0; p < 2; p++) {
            uint32_t r[4];
            ldm4(r, stb + OFF_B + (uint32_t)((wn * 32 + p * 16) * ROWB) + kb + boff);
            fb[2 * p][0] = r[0]; fb[2 * p][1] = r[1];
            fb[2 * p + 1][0] = r[2]; fb[2 * p + 1][1] = r[3];
        }
        #pragma unroll
        for (int mf = 0; mf < 4; mf++)
            #pragma unroll
            for (int nf = 0; nf < 4; nf++)
                mma16(acc[mf][nf], fa[mf], fb[nf]);
    };

    #pragma unroll
    for (int s = 0; s < NPIPE - 1; ++s) {
        load_stage(s);
        asm volatile("cp.async.commit_group;" ::: "memory");
    }

    for (int t = 0; t < NSTG; ++t) {
        asm volatile("cp.async.wait_group 2;" ::: "memory");
        __syncthreads();
        if (t + NPIPE - 1 < NSTG) load_stage(t + NPIPE - 1);
        asm volatile("cp.async.commit_group;" ::: "memory");

        const uint32_t stb = sb + (uint32_t)((t & (NPIPE - 1)) * STAGE_BYTES);
        compute_half(stb, 0);
        compute_half(stb, 1);
    }

    // ---------------- fused LIF epilogue + warp-aggregated band detect ----------------
    const size_t NE = (size_t)BATCH * HID;
    #pragma unroll
    for (int mf = 0; mf < 4; mf++) {
        #pragma unroll
        for (int rh = 0; rh < 2; rh++) {
            const int m = m0 + wm * 64 + mf * 16 + g + rh * 8;
            const size_t row = (size_t)m * HID;
            #pragma unroll
            for (int nf = 0; nf < 4; nf++) {
                const int n = n0 + wn * 32 + nf * 8 + 2 * t4;
                const size_t idx = row + n;
                float2 pc = *(const float2*)(preC  + idx);
                float2 pv = *(const float2*)(preV  + idx);
                float2 ps = *(const float2*)(S     + idx);
                float2 pt = *(const float2*)(preTh + idx);
                float2 mk = *(const float2*)(mask  + idx);
                float2 b1 = *(const float2*)(bpsp  + n);
                float2 b2 = *(const float2*)(brec  + n);

                float av[2]  = { acc[mf][nf][rh * 2 + 0], acc[mf][nf][rh * 2 + 1] };
                float pcv[2] = { pc.x, pc.y }, pvv[2] = { pv.x, pv.y };
                float psv[2] = { ps.x, ps.y }, ptv[2] = { pt.x, pt.y };
                float mkv[2] = { mk.x, mk.y };
                float b1v[2] = { b1.x, b1.y }, b2v[2] = { b2.x, b2.y };

                float sp[2], cu[2], vo[2], th[2];
                #pragma unroll
                for (int q = 0; q < 2; q++) {
                    float c = fmaf(0.5f, pcv[q], av[q] + b1v[q] + b2v[q]);
                    c *= mkv[q];
                    float v = fmaf(0.75f * pvv[q], (1.0f - psv[q]), c);
                    float s = (v > ptv[q]) ? 1.0f : 0.0f;
                    float tv = (s != 0.0f) ? (ptv[q] + 0.05f)
                                           : fmaxf(ptv[q] * 0.9f, 1.0f);
                    sp[q] = s; cu[q] = c; vo[q] = v; th[q] = tv;

                    const bool f = fabsf(v - ptv[q]) < DELTA;
                    const unsigned bal = __ballot_sync(0xFFFFFFFFu, f);
                    if (bal) {
                        const int leader = __ffs(bal) - 1;
                        uint32_t base = 0;
                        if (lane == leader)
                            base = atomicAdd(&g_count, (uint32_t)__popc(bal));
                        base = __shfl_sync(0xFFFFFFFFu, base, leader);
                        if (f) {
                            uint32_t pos = base + __popc(bal & ((1u << lane) - 1));
                            if (pos < LIST_CAP)
                                g_list[pos] = (uint32_t)((m << 11) | (n + q));
                        }
                    }
                }
                *(float2*)(out + idx) = make_float2(sp[0], sp[1]);
                if (sections > 1) *(float2*)(out + NE + idx)     = make_float2(sp[0], sp[1]);
                if (sections > 2) *(float2*)(out + 2 * NE + idx) = make_float2(cu[0], cu[1]);
                if (sections > 3) *(float2*)(out + 3 * NE + idx) = make_float2(vo[0], vo[1]);
                if (sections > 4) *(float2*)(out + 4 * NE + idx) = make_float2(th[0], th[1]);
            }
        }
    }
}

// ---- fixup: 2 elements/warp; weights = fp16 hi + fp16 residual, 16B loads ----
__global__ void fixup_k(const float* __restrict__ X, const float* __restrict__ S,
                        const float* __restrict__ preC, const float* __restrict__ preV,
                        const float* __restrict__ preTh, const float* __restrict__ mask,
                        const float* __restrict__ bpsp, const float* __restrict__ brec,
                        float* __restrict__ out, int sections)
{
    const int lane = threadIdx.x & 31;
    const int pairi = lane >> 4;         // which element of the pair
    const int hl = lane & 15;            // lane within 16-group
    const uint32_t wglob = (blockIdx.x * blockDim.x + threadIdx.x) >> 5;
    const uint32_t nw = (gridDim.x * blockDim.x) >> 5;
    uint32_t cnt = g_count;
    if (cnt > LIST_CAP) cnt = LIST_CAP;
    const size_t NE = (size_t)BATCH * HID;

    for (uint32_t i0 = wglob * 2; i0 < cnt; i0 += nw * 2) {
        const uint32_t i = i0 + (uint32_t)pairi;
        const bool act = (i < cnt);
        const uint32_t e = g_list[act ? i : i0];
        const int m = (int)(e >> 11), n = (int)(e & 2047);
        const float4* xr = (const float4*)(X + (size_t)m * INDIM);     // 512 f4
        const float4* sr = (const float4*)(S + (size_t)m * HID);       // 512 f4
        const uint4* wh = (const uint4*)(g_Bh + (size_t)n * KTOT);     // 512 x 8h
        const uint4* wl = (const uint4*)(g_Br + (size_t)n * KTOT);

        float a = 0.0f;
        #pragma unroll 2
        for (int k = hl; k < 256; k += 16) {          // X part: chunks 0..255
            uint4 H = wh[k], L = wl[k];
            float4 x0 = xr[2 * k], x1 = xr[2 * k + 1];
            float2 h0 = __half22float2(*(__half2*)&H.x), l0 = __half22float2(*(__half2*)&L.x);
            float2 h1 = __half22float2(*(__half2*)&H.y), l1 = __half22float2(*(__half2*)&L.y);
            float2 h2 = __half22float2(*(__half2*)&H.z), l2 = __half22float2(*(__half2*)&L.z);
            float2 h3 = __half22float2(*(__half2*)&H.w), l3 = __half22float2(*(__half2*)&L.w);
            a = fmaf(x0.x, h0.x + l0.x, a); a = fmaf(x0.y, h0.y + l0.y, a);
            a = fmaf(x0.z, h1.x + l1.x, a); a = fmaf(x0.w, h1.y + l1.y, a);
            a = fmaf(x1.x, h2.x + l2.x, a); a = fmaf(x1.y, h2.y + l2.y, a);
            a = fmaf(x1.z, h3.x + l3.x, a); a = fmaf(x1.w, h3.y + l3.y, a);
        }
        #pragma unroll 2
        for (int k = hl; k < 256; k += 16) {          // S part: chunks 256..511
            uint4 H = wh[256 + k], L = wl[256 + k];
            float4 x0 = sr[2 * k], x1 = sr[2 * k + 1];
            float2 h0 = __half22float2(*(__half2*)&H.x), l0 = __half22float2(*(__half2*)&L.x);
            float2 h1 = __half22float2(*(__half2*)&H.y), l1 = __half22float2(*(__half2*)&L.y);
            float2 h2 = __half22float2(*(__half2*)&H.z), l2 = __half22float2(*(__half2*)&L.z);
            float2 h3 = __half22float2(*(__half2*)&H.w), l3 = __half22float2(*(__half2*)&L.w);
            a = fmaf(x0.x, h0.x + l0.x, a); a = fmaf(x0.y, h0.y + l0.y, a);
            a = fmaf(x0.z, h1.x + l1.x, a); a = fmaf(x0.w, h1.y + l1.y, a);
            a = fmaf(x1.x, h2.x + l2.x, a); a = fmaf(x1.y, h2.y + l2.y, a);
            a = fmaf(x1.z, h3.x + l3.x, a); a = fmaf(x1.w, h3.y + l3.y, a);
        }
        #pragma unroll
        for (int o = 8; o; o >>= 1) a += __shfl_xor_sync(0xFFFFFFFFu, a, o);

        if (hl == 0 && act) {
            const size_t idx = (size_t)m * HID + n;
            float c = fmaf(0.5f, preC[idx], a + bpsp[n] + brec[n]);
            c *= mask[idx];
            float v = fmaf(0.75f * preV[idx], (1.0f - S[idx]), c);
            float pt = preTh[idx];
            float sp = (v > pt) ? 1.0f : 0.0f;
            float tv = (sp != 0.0f) ? (pt + 0.05f) : fmaxf(pt * 0.9f, 1.0f);
            out[idx] = sp;
            if (sections > 1) out[NE + idx]     = sp;
            if (sections > 2) out[2 * NE + idx] = c;
            if (sections > 3) out[3 * NE + idx] = v;
            if (sections > 4) out[4 * NE + idx] = tv;
        }
    }
}

// ---------------- launch ----------------
extern "C" void kernel_launch(void* const* d_in, const int* in_sizes, int n_in,
                              void* d_out, int out_size) {
    const float* X     = (const float*)d_in[0];
    const float* S     = (const float*)d_in[1];
    const float* preC  = (const float*)d_in[2];
    const float* preV  = (const float*)d_in[3];
    const float* preTh = (const float*)d_in[4];
    const float* mk    = (const float*)d_in[5];
    const float* Wpsp  = (const float*)d_in[6];
    const float* bpsp  = (const float*)d_in[7];
    const float* Wrec  = (const float*)d_in[8];
    const float* brec  = (const float*)d_in[9];

    const long long NE = (long long)BATCH * HID;
    int sections = (int)((long long)out_size / NE);
    if (sections < 1) sections = 1;
    if (sections > 5) sections = 5;

    cudaFuncSetAttribute(gemm_lif, cudaFuncAttributeMaxDynamicSharedMemorySize,
                         SMEM_BYTES);

    const size_t n2 = (size_t)BATCH * KTOT / 2;
    build_a_k<<<(unsigned)((n2 + 255) / 256), 256>>>(X, S);
    dim3 wg(HID / 32, KTOT / 2 / 32, 2), wb(32, 8);
    trans_w_k<<<wg, wb>>>(Wpsp, Wrec);

    dim3 grid(HID / BN, BATCH / BM);   // (16, 32) = 512 CTAs
    gemm_lif<<<grid, 256, SMEM_BYTES>>>(S, preC, preV, preTh, mk, bpsp, brec,
                                        (float*)d_out, sections);
    fixup_k<<<1024, 256>>>(X, S, preC, preV, preTh, mk, bpsp, brec,
                           (float*)d_out, sections);
}

// round 16
// speedup vs baseline: 1.4375x; 1.4375x over previous
#include <cuda_runtime.h>
#include <cuda_fp16.h>
#include <cstdint>

#define BATCH 4096
#define INDIM 2048
#define HID   2048
#define KTOT  4096

#define BM 128
#define BN 128
#define BK 32
#define NSTG (KTOT / BK)                 // 128 k-chunks

#define ROWB 80                          // 64B data + 16B pad per row
#define TILE_BYTES (128 * ROWB)          // 10240
#define OFF_A 0
#define OFF_B TILE_BYTES
#define STAGE_BYTES (2 * TILE_BYTES)     // 20480
#define NPIPE 4
#define SMEM_BYTES (NPIPE * STAGE_BYTES) // 81920

#define DELTA    3e-3f
#define LIST_CAP (1u << 21)

// ---------------- device scratch ----------------
__device__ __half g_Ah[(size_t)BATCH * KTOT];    // [m][k]: fp16(X) | fp16(S)
__device__ __half g_Bh[(size_t)HID * KTOT];      // [n][k]: fp16(W^T) concat
__device__ float  g_WfT[(size_t)HID * KTOT];     // [n][k]: exact fp32 W^T concat
__device__ uint32_t g_count;
__device__ uint32_t g_list[LIST_CAP];

// ---------------- helpers ----------------
__device__ __forceinline__ uint32_t s2u(const void* p) {
    uint32_t a;
    asm("{ .reg .u64 t; cvta.to.shared.u64 t, %1; cvt.u32.u64 %0, t; }"
        : "=r"(a) : "l"(p));
    return a;
}
__device__ __forceinline__ void cp16(uint32_t d, const void* s) {
    asm volatile("cp.async.cg.shared.global [%0], [%1], 16;" :: "r"(d), "l"(s));
}
__device__ __forceinline__ void ldm4(uint32_t* r, uint32_t addr) {
    asm volatile("ldmatrix.sync.aligned.m8n8.x4.shared.b16 {%0,%1,%2,%3}, [%4];"
                 : "=r"(r[0]), "=r"(r[1]), "=r"(r[2]), "=r"(r[3]) : "r"(addr));
}
__device__ __forceinline__ void mma16(float* d, const uint32_t* a, const uint32_t* b) {
    asm volatile(
        "mma.sync.aligned.m16n8k16.row.col.f32.f16.f16.f32 "
        "{%0,%1,%2,%3},{%4,%5,%6,%7},{%8,%9},{%0,%1,%2,%3};"
        : "+f"(d[0]), "+f"(d[1]), "+f"(d[2]), "+f"(d[3])
        : "r"(a[0]), "r"(a[1]), "r"(a[2]), "r"(a[3]), "r"(b[0]), "r"(b[1]));
}

// ---------------- pre-kernels ----------------
__global__ void build_a_k(const float* __restrict__ X, const float* __restrict__ S) {
    size_t i = (size_t)blockIdx.x * blockDim.x + threadIdx.x;   // half2 index
    if (i == 0) g_count = 0;
    const size_t n2 = (size_t)BATCH * KTOT / 2;
    if (i >= n2) return;
    const int m = (int)(i >> 11);
    const int k = (int)(i & 2047) * 2;
    float2 v;
    if (k < INDIM) v = *(const float2*)(X + (size_t)m * INDIM + k);
    else           v = *(const float2*)(S + (size_t)m * HID + (k - INDIM));
    ((__half2*)g_Ah)[i] = __floats2half2_rn(v.x, v.y);
}
__global__ void trans_w_k(const float* __restrict__ Wpsp,
                          const float* __restrict__ Wrec) {
    __shared__ float tile[32][33];
    const float* W = blockIdx.z ? Wrec : Wpsp;
    const int off = blockIdx.z ? INDIM : 0;
    const int n0 = blockIdx.x * 32, k0 = blockIdx.y * 32;
    const int tx = threadIdx.x, ty = threadIdx.y;
    #pragma unroll
    for (int r = ty; r < 32; r += 8)
        tile[r][tx] = W[(size_t)(k0 + r) * HID + n0 + tx];
    __syncthreads();
    #pragma unroll
    for (int r = ty; r < 32; r += 8) {
        float v = tile[tx][r];                    // = W[k0+tx][n0+r]
        size_t o = (size_t)(n0 + r) * KTOT + off + k0 + tx;
        g_Bh[o]  = __float2half_rn(v);
        g_WfT[o] = v;
    }
}

// ---------------- main fused GEMM + LIF + band detect ----------------
__global__ void __launch_bounds__(256, 2)
gemm_lif(const float* __restrict__ S, const float* __restrict__ preC,
         const float* __restrict__ preV, const float* __restrict__ preTh,
         const float* __restrict__ mask, const float* __restrict__ bpsp,
         const float* __restrict__ brec, float* __restrict__ out, int sections)
{
    extern __shared__ char smem[];
    const uint32_t sb = s2u(smem);
    const int tid = threadIdx.x;
    const int lane = tid & 31, warp = tid >> 5;
    const int g = lane >> 2, t4 = lane & 3;
    const int wm = warp >> 2, wn = warp & 3;            // 2 x 4 warps, 64x32 tiles
    const int m0 = blockIdx.y * BM, n0 = blockIdx.x * BN;

    const uint32_t aoff = (uint32_t)((lane & 15) * ROWB + (lane >> 4) * 16);
    const uint32_t boff =
        (uint32_t)((((lane & 7) + ((lane >> 4) & 1) * 8)) * ROWB + ((lane >> 3) & 1) * 16);

    float acc[4][4][4];
    #pragma unroll
    for (int i = 0; i < 4; i++)
        #pragma unroll
        for (int j = 0; j < 4; j++)
            #pragma unroll
            for (int q = 0; q < 4; q++) acc[i][j][q] = 0.0f;

    auto load_stage = [&](int t) {
        const uint32_t base = sb + (uint32_t)((t & (NPIPE - 1)) * STAGE_BYTES);
        const int k0 = t * BK;
        #pragma unroll
        for (int i = 0; i < 2; i++) {
            const int u = tid + i * 256;
            const int r = u >> 2, c = u & 3;
            const uint32_t d = (uint32_t)(r * ROWB + c * 16);
            cp16(base + OFF_A + d, g_Ah + (size_t)(m0 + r) * KTOT + k0 + c * 8);
            cp16(base + OFF_B + d, g_Bh + (size_t)(n0 + r) * KTOT + k0 + c * 8);
        }
    };

    uint32_t fa[4][4], fb[4][2];
    auto compute_half = [&](uint32_t stb, int h) {
        const uint32_t kb = (uint32_t)(h * 32);
        #pragma unroll
        for (int mf = 0; mf < 4; mf++)
            ldm4(fa[mf], stb + OFF_A + (uint32_t)((wm * 64 + mf * 16) * ROWB) + kb + aoff);
        #pragma unroll
        for (int p = 0; p < 2; p++) {
            uint32_t r[4];
            ldm4(r, stb + OFF_B + (uint32_t)((wn * 32 + p * 16) * ROWB) + kb + boff);
            fb[2 * p][0] = r[0]; fb[2 * p][1] = r[1];
            fb[2 * p + 1][0] = r[2]; fb[2 * p + 1][1] = r[3];
        }
        #pragma unroll
        for (int mf = 0; mf < 4; mf++)
            #pragma unroll
            for (int nf = 0; nf < 4; nf++)
                mma16(acc[mf][nf], fa[mf], fb[nf]);
    };

    #pragma unroll
    for (int s = 0; s < NPIPE - 1; ++s) {
        load_stage(s);
        asm volatile("cp.async.commit_group;" ::: "memory");
    }

    for (int t = 0; t < NSTG; ++t) {
        asm volatile("cp.async.wait_group 2;" ::: "memory");
        __syncthreads();
        if (t + NPIPE - 1 < NSTG) load_stage(t + NPIPE - 1);
        asm volatile("cp.async.commit_group;" ::: "memory");

        const uint32_t stb = sb + (uint32_t)((t & (NPIPE - 1)) * STAGE_BYTES);
        compute_half(stb, 0);
        compute_half(stb, 1);
    }

    // ---------------- fused LIF epilogue + warp-aggregated band detect ----------------
    const size_t NE = (size_t)BATCH * HID;
    #pragma unroll
    for (int mf = 0; mf < 4; mf++) {
        #pragma unroll
        for (int rh = 0; rh < 2; rh++) {
            const int m = m0 + wm * 64 + mf * 16 + g + rh * 8;
            const size_t row = (size_t)m * HID;
            #pragma unroll
            for (int nf = 0; nf < 4; nf++) {
                const int n = n0 + wn * 32 + nf * 8 + 2 * t4;
                const size_t idx = row + n;
                float2 pc = *(const float2*)(preC  + idx);
                float2 pv = *(const float2*)(preV  + idx);
                float2 ps = *(const float2*)(S     + idx);
                float2 pt = *(const float2*)(preTh + idx);
                float2 mk = *(const float2*)(mask  + idx);
                float2 b1 = *(const float2*)(bpsp  + n);
                float2 b2 = *(const float2*)(brec  + n);

                float av[2]  = { acc[mf][nf][rh * 2 + 0], acc[mf][nf][rh * 2 + 1] };
                float pcv[2] = { pc.x, pc.y }, pvv[2] = { pv.x, pv.y };
                float psv[2] = { ps.x, ps.y }, ptv[2] = { pt.x, pt.y };
                float mkv[2] = { mk.x, mk.y };
                float b1v[2] = { b1.x, b1.y }, b2v[2] = { b2.x, b2.y };

                float sp[2], cu[2], vo[2], th[2];
                #pragma unroll
                for (int q = 0; q < 2; q++) {
                    float c = fmaf(0.5f, pcv[q], av[q] + b1v[q] + b2v[q]);
                    c *= mkv[q];
                    float v = fmaf(0.75f * pvv[q], (1.0f - psv[q]), c);
                    float s = (v > ptv[q]) ? 1.0f : 0.0f;
                    float tv = (s != 0.0f) ? (ptv[q] + 0.05f)
                                           : fmaxf(ptv[q] * 0.9f, 1.0f);
                    sp[q] = s; cu[q] = c; vo[q] = v; th[q] = tv;

                    const bool f = fabsf(v - ptv[q]) < DELTA;
                    const unsigned bal = __ballot_sync(0xFFFFFFFFu, f);
                    if (bal) {
                        const int leader = __ffs(bal) - 1;
                        uint32_t base = 0;
                        if (lane == leader)
                            base = atomicAdd(&g_count, (uint32_t)__popc(bal));
                        base = __shfl_sync(0xFFFFFFFFu, base, leader);
                        if (f) {
                            uint32_t pos = base + __popc(bal & ((1u << lane) - 1));
                            if (pos < LIST_CAP)
                                g_list[pos] = (uint32_t)((m << 11) | (n + q));
                        }
                    }
                }
                *(float2*)(out + idx) = make_float2(sp[0], sp[1]);
                if (sections > 1) *(float2*)(out + NE + idx)     = make_float2(sp[0], sp[1]);
                if (sections > 2) *(float2*)(out + 2 * NE + idx) = make_float2(cu[0], cu[1]);
                if (sections > 3) *(float2*)(out + 3 * NE + idx) = make_float2(vo[0], vo[1]);
                if (sections > 4) *(float2*)(out + 4 * NE + idx) = make_float2(th[0], th[1]);
            }
        }
    }
}

// ---------------- exact fp32 fixup of near-threshold elements ----------------
__global__ void fixup_k(const float* __restrict__ X, const float* __restrict__ S,
                        const float* __restrict__ preC, const float* __restrict__ preV,
                        const float* __restrict__ preTh, const float* __restrict__ mask,
                        const float* __restrict__ bpsp, const float* __restrict__ brec,
                        float* __restrict__ out, int sections)
{
    const int lane = threadIdx.x & 31;
    const uint32_t wglob = (blockIdx.x * blockDim.x + threadIdx.x) >> 5;
    const uint32_t nw = (gridDim.x * blockDim.x) >> 5;
    uint32_t cnt = g_count;
    if (cnt > LIST_CAP) cnt = LIST_CAP;
    const size_t NE = (size_t)BATCH * HID;

    for (uint32_t i = wglob; i < cnt; i += nw) {
        const uint32_t e = g_list[i];
        const int m = (int)(e >> 11), n = (int)(e & 2047);
        const float4* xr = (const float4*)(X + (size_t)m * INDIM);
        const float4* sr = (const float4*)(S + (size_t)m * HID);
        const float4* wr = (const float4*)(g_WfT + (size_t)n * KTOT);
        const float4* rr = wr + INDIM / 4;
        float a = 0.0f;
        #pragma unroll 4
        for (int k = lane; k < INDIM / 4; k += 32) {
            float4 x = xr[k], w = wr[k];
            a = fmaf(x.x, w.x, a); a = fmaf(x.y, w.y, a);
            a = fmaf(x.z, w.z, a); a = fmaf(x.w, w.w, a);
        }
        #pragma unroll 4
        for (int k = lane; k < HID / 4; k += 32) {
            float4 x = sr[k], w = rr[k];
            a = fmaf(x.x, w.x, a); a = fmaf(x.y, w.y, a);
            a = fmaf(x.z, w.z, a); a = fmaf(x.w, w.w, a);
        }
        #pragma unroll
        for (int o = 16; o; o >>= 1) a += __shfl_xor_sync(0xFFFFFFFFu, a, o);

        if (lane == 0) {
            const size_t idx = (size_t)m * HID + n;
            float c = fmaf(0.5f, preC[idx], a + bpsp[n] + brec[n]);
            c *= mask[idx];
            float v = fmaf(0.75f * preV[idx], (1.0f - S[idx]), c);
            float pt = preTh[idx];
            float sp = (v > pt) ? 1.0f : 0.0f;
            float tv = (sp != 0.0f) ? (pt + 0.05f) : fmaxf(pt * 0.9f, 1.0f);
            out[idx] = sp;
            if (sections > 1) out[NE + idx]     = sp;
            if (sections > 2) out[2 * NE + idx] = c;
            if (sections > 3) out[3 * NE + idx] = v;
            if (sections > 4) out[4 * NE + idx] = tv;
        }
    }
}

// ---------------- launch ----------------
extern "C" void kernel_launch(void* const* d_in, const int* in_sizes, int n_in,
                              void* d_out, int out_size) {
    const float* X     = (const float*)d_in[0];
    const float* S     = (const float*)d_in[1];
    const float* preC  = (const float*)d_in[2];
    const float* preV  = (const float*)d_in[3];
    const float* preTh = (const float*)d_in[4];
    const float* mk    = (const float*)d_in[5];
    const float* Wpsp  = (const float*)d_in[6];
    const float* bpsp  = (const float*)d_in[7];
    const float* Wrec  = (const float*)d_in[8];
    const float* brec  = (const float*)d_in[9];

    const long long NE = (long long)BATCH * HID;
    int sections = (int)((long long)out_size / NE);
    if (sections < 1) sections = 1;
    if (sections > 5) sections = 5;

    cudaFuncSetAttribute(gemm_lif, cudaFuncAttributeMaxDynamicSharedMemorySize,
                         SMEM_BYTES);

    const size_t n2 = (size_t)BATCH * KTOT / 2;
    build_a_k<<<(unsigned)((n2 + 255) / 256), 256>>>(X, S);
    dim3 wg(HID / 32, KTOT / 2 / 32, 2), wb(32, 8);
    trans_w_k<<<wg, wb>>>(Wpsp, Wrec);

    dim3 grid(HID / BN, BATCH / BM);   // (16, 32) = 512 CTAs
    gemm_lif<<<grid, 256, SMEM_BYTES>>>(S, preC, preV, preTh, mk, bpsp, brec,
                                        (float*)d_out, sections);
    fixup_k<<<512, 256>>>(X, S, preC, preV, preTh, mk, bpsp, brec,
                          (float*)d_out, sections);
}

// round 17
// speedup vs baseline: 1.4425x; 1.0035x over previous
#include <cuda_runtime.h>
#include <cuda_fp16.h>
#include <cstdint>

#define BATCH 4096
#define INDIM 2048
#define HID   2048
#define KTOT  4096

#define BM 128
#define BN 128
#define BK 32
#define NSTG (KTOT / BK)                 // 128 k-chunks

#define ROWB 80                          // 64B data + 16B pad per row
#define TILE_BYTES (128 * ROWB)          // 10240
#define OFF_A 0
#define OFF_B TILE_BYTES
#define STAGE_BYTES (2 * TILE_BYTES)     // 20480
#define NPIPE 4
#define SMEM_BYTES (NPIPE * STAGE_BYTES) // 81920

#define DELTA    3e-3f
#define LIST_CAP (1u << 21)

// prep_k grid partition
#define NB_A ((BATCH * KTOT / 2) / 256)          // 16384 blocks: build A
#define NB_W ((HID / 32) * (KTOT / 2 / 32))      // 4096 blocks per weight matrix

// ---------------- device scratch ----------------
__device__ __half g_Ah[(size_t)BATCH * KTOT];    // [m][k]: fp16(X) | fp16(S)
__device__ __half g_Bh[(size_t)HID * KTOT];      // [n][k]: fp16(W^T) concat
__device__ float  g_WfT[(size_t)HID * KTOT];     // [n][k]: exact fp32 W^T concat
__device__ uint32_t g_count;
__device__ uint32_t g_list[LIST_CAP];

// ---------------- helpers ----------------
__device__ __forceinline__ uint32_t s2u(const void* p) {
    uint32_t a;
    asm("{ .reg .u64 t; cvta.to.shared.u64 t, %1; cvt.u32.u64 %0, t; }"
        : "=r"(a) : "l"(p));
    return a;
}
__device__ __forceinline__ void cp16(uint32_t d, const void* s) {
    asm volatile("cp.async.cg.shared.global [%0], [%1], 16;" :: "r"(d), "l"(s));
}
__device__ __forceinline__ void ldm4(uint32_t* r, uint32_t addr) {
    asm volatile("ldmatrix.sync.aligned.m8n8.x4.shared.b16 {%0,%1,%2,%3}, [%4];"
                 : "=r"(r[0]), "=r"(r[1]), "=r"(r[2]), "=r"(r[3]) : "r"(addr));
}
__device__ __forceinline__ void mma16(float* d, const uint32_t* a, const uint32_t* b) {
    asm volatile(
        "mma.sync.aligned.m16n8k16.row.col.f32.f16.f16.f32 "
        "{%0,%1,%2,%3},{%4,%5,%6,%7},{%8,%9},{%0,%1,%2,%3};"
        : "+f"(d[0]), "+f"(d[1]), "+f"(d[2]), "+f"(d[3])
        : "r"(a[0]), "r"(a[1]), "r"(a[2]), "r"(a[3]), "r"(b[0]), "r"(b[1]));
}

// ---------------- fused pre-kernel: build A + transpose/split W ----------------
__global__ void prep_k(const float* __restrict__ X, const float* __restrict__ S,
                       const float* __restrict__ Wpsp, const float* __restrict__ Wrec)
{
    __shared__ float tile[32][33];
    const int bid = blockIdx.x;
    const int th = threadIdx.x;

    if (bid < NB_A) {
        // --- build A = [fp16(X) | fp16(S)] ---
        size_t i = (size_t)bid * 256 + th;        // half2 index
        if (i == 0) g_count = 0;
        const int m = (int)(i >> 11);
        const int k = (int)(i & 2047) * 2;
        float2 v;
        if (k < INDIM) v = *(const float2*)(X + (size_t)m * INDIM + k);
        else           v = *(const float2*)(S + (size_t)m * HID + (k - INDIM));
        ((__half2*)g_Ah)[i] = __floats2half2_rn(v.x, v.y);
    } else {
        // --- transpose W [k][n] -> [n][k], fp16 + fp32 copies ---
        const int b2 = bid - NB_A;
        const int which = b2 >> 12;               // 0: Wpsp, 1: Wrec
        const int rem = b2 & (NB_W - 1);
        const float* W = which ? Wrec : Wpsp;
        const int off = which ? INDIM : 0;
        const int n0 = (rem & 63) * 32;
        const int k0 = (rem >> 6) * 32;
        const int tx = th & 31, ty = th >> 5;     // 32 x 8
        #pragma unroll
        for (int r = ty; r < 32; r += 8)
            tile[r][tx] = W[(size_t)(k0 + r) * HID + n0 + tx];
        __syncthreads();
        #pragma unroll
        for (int r = ty; r < 32; r += 8) {
            float v = tile[tx][r];                // = W[k0+tx][n0+r]
            size_t o = (size_t)(n0 + r) * KTOT + off + k0 + tx;
            g_Bh[o]  = __float2half_rn(v);
            g_WfT[o] = v;
        }
    }
}

// ---------------- main fused GEMM + LIF + band detect ----------------
__global__ void __launch_bounds__(256, 2)
gemm_lif(const float* __restrict__ S, const float* __restrict__ preC,
         const float* __restrict__ preV, const float* __restrict__ preTh,
         const float* __restrict__ mask, const float* __restrict__ bpsp,
         const float* __restrict__ brec, float* __restrict__ out, int sections)
{
    extern __shared__ char smem[];
    const uint32_t sb = s2u(smem);
    const int tid = threadIdx.x;
    const int lane = tid & 31, warp = tid >> 5;
    const int g = lane >> 2, t4 = lane & 3;
    const int wm = warp >> 2, wn = warp & 3;            // 2 x 4 warps, 64x32 tiles
    const int m0 = blockIdx.y * BM, n0 = blockIdx.x * BN;

    const uint32_t aoff = (uint32_t)((lane & 15) * ROWB + (lane >> 4) * 16);
    const uint32_t boff =
        (uint32_t)((((lane & 7) + ((lane >> 4) & 1) * 8)) * ROWB + ((lane >> 3) & 1) * 16);

    float acc[4][4][4];
    #pragma unroll
    for (int i = 0; i < 4; i++)
        #pragma unroll
        for (int j = 0; j < 4; j++)
            #pragma unroll
            for (int q = 0; q < 4; q++) acc[i][j][q] = 0.0f;

    auto load_stage = [&](int t) {
        const uint32_t base = sb + (uint32_t)((t & (NPIPE - 1)) * STAGE_BYTES);
        const int k0 = t * BK;
        #pragma unroll
        for (int i = 0; i < 2; i++) {
            const int u = tid + i * 256;
            const int r = u >> 2, c = u & 3;
            const uint32_t d = (uint32_t)(r * ROWB + c * 16);
            cp16(base + OFF_A + d, g_Ah + (size_t)(m0 + r) * KTOT + k0 + c * 8);
            cp16(base + OFF_B + d, g_Bh + (size_t)(n0 + r) * KTOT + k0 + c * 8);
        }
    };

    uint32_t fa[4][4], fb[4][2];
    auto compute_half = [&](uint32_t stb, int h) {
        const uint32_t kb = (uint32_t)(h * 32);
        #pragma unroll
        for (int mf = 0; mf < 4; mf++)
            ldm4(fa[mf], stb + OFF_A + (uint32_t)((wm * 64 + mf * 16) * ROWB) + kb + aoff);
        #pragma unroll
        for (int p = 0; p < 2; p++) {
            uint32_t r[4];
            ldm4(r, stb + OFF_B + (uint32_t)((wn * 32 + p * 16) * ROWB) + kb + boff);
            fb[2 * p][0] = r[0]; fb[2 * p][1] = r[1];
            fb[2 * p + 1][0] = r[2]; fb[2 * p + 1][1] = r[3];
        }
        #pragma unroll
        for (int mf = 0; mf < 4; mf++)
            #pragma unroll
            for (int nf = 0; nf < 4; nf++)
                mma16(acc[mf][nf], fa[mf], fb[nf]);
    };

    #pragma unroll
    for (int s = 0; s < NPIPE - 1; ++s) {
        load_stage(s);
        asm volatile("cp.async.commit_group;" ::: "memory");
    }

    for (int t = 0; t < NSTG; ++t) {
        asm volatile("cp.async.wait_group 2;" ::: "memory");
        __syncthreads();
        if (t + NPIPE - 1 < NSTG) load_stage(t + NPIPE - 1);
        asm volatile("cp.async.commit_group;" ::: "memory");

        const uint32_t stb = sb + (uint32_t)((t & (NPIPE - 1)) * STAGE_BYTES);
        compute_half(stb, 0);
        compute_half(stb, 1);
    }

    // ---------------- fused LIF epilogue + warp-aggregated band detect ----------------
    const size_t NE = (size_t)BATCH * HID;
    #pragma unroll
    for (int mf = 0; mf < 4; mf++) {
        #pragma unroll
        for (int rh = 0; rh < 2; rh++) {
            const int m = m0 + wm * 64 + mf * 16 + g + rh * 8;
            const size_t row = (size_t)m * HID;
            #pragma unroll
            for (int nf = 0; nf < 4; nf++) {
                const int n = n0 + wn * 32 + nf * 8 + 2 * t4;
                const size_t idx = row + n;
                float2 pc = *(const float2*)(preC  + idx);
                float2 pv = *(const float2*)(preV  + idx);
                float2 ps = *(const float2*)(S     + idx);
                float2 pt = *(const float2*)(preTh + idx);
                float2 mk = *(const float2*)(mask  + idx);
                float2 b1 = *(const float2*)(bpsp  + n);
                float2 b2 = *(const float2*)(brec  + n);

                float av[2]  = { acc[mf][nf][rh * 2 + 0], acc[mf][nf][rh * 2 + 1] };
                float pcv[2] = { pc.x, pc.y }, pvv[2] = { pv.x, pv.y };
                float psv[2] = { ps.x, ps.y }, ptv[2] = { pt.x, pt.y };
                float mkv[2] = { mk.x, mk.y };
                float b1v[2] = { b1.x, b1.y }, b2v[2] = { b2.x, b2.y };

                float sp[2], cu[2], vo[2], th[2];
                bool fq[2];
                #pragma unroll
                for (int q = 0; q < 2; q++) {
                    float c = fmaf(0.5f, pcv[q], av[q] + b1v[q] + b2v[q]);
                    c *= mkv[q];
                    float v = fmaf(0.75f * pvv[q], (1.0f - psv[q]), c);
                    float s = (v > ptv[q]) ? 1.0f : 0.0f;
                    float tv = (s != 0.0f) ? (ptv[q] + 0.05f)
                                           : fmaxf(ptv[q] * 0.9f, 1.0f);
                    sp[q] = s; cu[q] = c; vo[q] = v; th[q] = tv;
                    fq[q] = fabsf(v - ptv[q]) < DELTA;
                }

                // one aggregated append for both q values
                const unsigned bal0 = __ballot_sync(0xFFFFFFFFu, fq[0]);
                const unsigned bal1 = __ballot_sync(0xFFFFFFFFu, fq[1]);
                if (bal0 | bal1) {
                    const unsigned both = bal0 | bal1;
                    const int leader = __ffs(both) - 1;
                    uint32_t base = 0;
                    if (lane == leader)
                        base = atomicAdd(&g_count,
                                         (uint32_t)(__popc(bal0) + __popc(bal1)));
                    base = __shfl_sync(0xFFFFFFFFu, base, leader);
                    const uint32_t n0cnt = (uint32_t)__popc(bal0);
                    if (fq[0]) {
                        uint32_t pos = base + __popc(bal0 & ((1u << lane) - 1));
                        if (pos < LIST_CAP)
                            g_list[pos] = (uint32_t)((m << 11) | n);
                    }
                    if (fq[1]) {
                        uint32_t pos = base + n0cnt + __popc(bal1 & ((1u << lane) - 1));
                        if (pos < LIST_CAP)
                            g_list[pos] = (uint32_t)((m << 11) | (n + 1));
                    }
                }

                *(float2*)(out + idx) = make_float2(sp[0], sp[1]);
                if (sections > 1) *(float2*)(out + NE + idx)     = make_float2(sp[0], sp[1]);
                if (sections > 2) *(float2*)(out + 2 * NE + idx) = make_float2(cu[0], cu[1]);
                if (sections > 3) *(float2*)(out + 3 * NE + idx) = make_float2(vo[0], vo[1]);
                if (sections > 4) *(float2*)(out + 4 * NE + idx) = make_float2(th[0], th[1]);
            }
        }
    }
}

// ---------------- exact fp32 fixup of near-threshold elements ----------------
__global__ void fixup_k(const float* __restrict__ X, const float* __restrict__ S,
                        const float* __restrict__ preC, const float* __restrict__ preV,
                        const float* __restrict__ preTh, const float* __restrict__ mask,
                        const float* __restrict__ bpsp, const float* __restrict__ brec,
                        float* __restrict__ out, int sections)
{
    const int lane = threadIdx.x & 31;
    const uint32_t wglob = (blockIdx.x * blockDim.x + threadIdx.x) >> 5;
    const uint32_t nw = (gridDim.x * blockDim.x) >> 5;
    uint32_t cnt = g_count;
    if (cnt > LIST_CAP) cnt = LIST_CAP;
    const size_t NE = (size_t)BATCH * HID;

    for (uint32_t i = wglob; i < cnt; i += nw) {
        const uint32_t e = g_list[i];
        const int m = (int)(e >> 11), n = (int)(e & 2047);
        const float4* xr = (const float4*)(X + (size_t)m * INDIM);
        const float4* sr = (const float4*)(S + (size_t)m * HID);
        const float4* wr = (const float4*)(g_WfT + (size_t)n * KTOT);
        const float4* rr = wr + INDIM / 4;
        float a = 0.0f;
        #pragma unroll 4
        for (int k = lane; k < INDIM / 4; k += 32) {
            float4 x = xr[k], w = wr[k];
            a = fmaf(x.x, w.x, a); a = fmaf(x.y, w.y, a);
            a = fmaf(x.z, w.z, a); a = fmaf(x.w, w.w, a);
        }
        #pragma unroll 4
        for (int k = lane; k < HID / 4; k += 32) {
            float4 x = sr[k], w = rr[k];
            a = fmaf(x.x, w.x, a); a = fmaf(x.y, w.y, a);
            a = fmaf(x.z, w.z, a); a = fmaf(x.w, w.w, a);
        }
        #pragma unroll
        for (int o = 16; o; o >>= 1) a += __shfl_xor_sync(0xFFFFFFFFu, a, o);

        if (lane == 0) {
            const size_t idx = (size_t)m * HID + n;
            float c = fmaf(0.5f, preC[idx], a + bpsp[n] + brec[n]);
            c *= mask[idx];
            float v = fmaf(0.75f * preV[idx], (1.0f - S[idx]), c);
            float pt = preTh[idx];
            float sp = (v > pt) ? 1.0f : 0.0f;
            float tv = (sp != 0.0f) ? (pt + 0.05f) : fmaxf(pt * 0.9f, 1.0f);
            out[idx] = sp;
            if (sections > 1) out[NE + idx]     = sp;
            if (sections > 2) out[2 * NE + idx] = c;
            if (sections > 3) out[3 * NE + idx] = v;
            if (sections > 4) out[4 * NE + idx] = tv;
        }
    }
}

// ---------------- launch ----------------
extern "C" void kernel_launch(void* const* d_in, const int* in_sizes, int n_in,
                              void* d_out, int out_size) {
    const float* X     = (const float*)d_in[0];
    const float* S     = (const float*)d_in[1];
    const float* preC  = (const float*)d_in[2];
    const float* preV  = (const float*)d_in[3];
    const float* preTh = (const float*)d_in[4];
    const float* mk    = (const float*)d_in[5];
    const float* Wpsp  = (const float*)d_in[6];
    const float* bpsp  = (const float*)d_in[7];
    const float* Wrec  = (const float*)d_in[8];
    const float* brec  = (const float*)d_in[9];

    const long long NE = (long long)BATCH * HID;
    int sections = (int)((long long)out_size / NE);
    if (sections < 1) sections = 1;
    if (sections > 5) sections = 5;

    cudaFuncSetAttribute(gemm_lif, cudaFuncAttributeMaxDynamicSharedMemorySize,
                         SMEM_BYTES);

    prep_k<<<NB_A + 2 * NB_W, 256>>>(X, S, Wpsp, Wrec);   // 24576 blocks, one launch

    dim3 grid(HID / BN, BATCH / BM);   // (16, 32) = 512 CTAs
    gemm_lif<<<grid, 256, SMEM_BYTES>>>(S, preC, preV, preTh, mk, bpsp, brec,
                                        (float*)d_out, sections);
    fixup_k<<<512, 256>>>(X, S, preC, preV, preTh, mk, bpsp, brec,
                          (float*)d_out, sections);
}